// round 1
// baseline (speedup 1.0000x reference)
#include <cuda_runtime.h>

// Problem constants (fixed by the reference)
#define B_  4096
#define F_  784
#define D_  10000
#define C_  10
#define NW  313           // ceil(D/32) packed centroid words per class

// GEMM tiling
#define BM  64
#define BN  256
#define BK  16

__device__ unsigned g_centPacked[C_ * NW];

// ---------------------------------------------------------------------------
// Pack binary centroids into bitfields: bit l of word w (class c) = centroid
// value at d = 32*w + l. Recomputed every launch (deterministic, ~us cost).
// ---------------------------------------------------------------------------
__global__ void pack_centroids_kernel(const float* __restrict__ cent) {
    int idx = blockIdx.x * blockDim.x + threadIdx.x;
    if (idx >= C_ * NW) return;
    int c = idx / NW;
    int w = idx % NW;
    int d0 = w * 32;
    unsigned word = 0u;
    #pragma unroll
    for (int b = 0; b < 32; b++) {
        int d = d0 + b;
        if (d < D_ && cent[c * D_ + d] > 0.5f) word |= (1u << b);
    }
    g_centPacked[idx] = word;
}

__global__ void zero_out_kernel(float* __restrict__ out) {
    int i = blockIdx.x * blockDim.x + threadIdx.x;
    if (i < B_ * C_) out[i] = 0.0f;
}

// ---------------------------------------------------------------------------
// Fused: fp32 GEMM (x = samples-0.5 times bhv^T), sign-binarize via ballot,
// XOR-popcount against packed centroids, atomic accumulate -hamming.
//
// Block tile: BM=64 rows (b) x BN=256 cols (d). 8 warps: 4 along b x 2 along d.
// Warp tile: 16 b x 128 d. Lane l owns d = wd + l + 32*j, j=0..3 -> ballot
// over the warp directly yields the packed 32-bit sign word for consecutive d.
// ---------------------------------------------------------------------------
__global__ __launch_bounds__(256, 2)
void hdc_fused_kernel(const float* __restrict__ samples,
                      const float* __restrict__ bhv,
                      float* __restrict__ out) {
    __shared__ float As[BM][BK];        // [b][k]
    __shared__ float Bs[BK][BN];        // [k][d]  (transposed on store)

    const int tid  = threadIdx.x;
    const int warp = tid >> 5;
    const int lane = tid & 31;
    const int wb   = (warp >> 1) * 16;     // warp b offset in tile
    const int wd   = (warp & 1) * 128;     // warp d offset in tile
    const int blockB = blockIdx.y * BM;
    const int blockD = blockIdx.x * BN;

    float acc[16][4];
    #pragma unroll
    for (int i = 0; i < 16; i++)
        #pragma unroll
        for (int j = 0; j < 4; j++)
            acc[i][j] = 0.0f;

    // A-load mapping: one float4 per thread per tile
    const int arow = tid >> 2;             // 0..63
    const int akg  = (tid & 3) * 4;        // k sub-offset 0,4,8,12

    for (int k0 = 0; k0 < F_; k0 += BK) {
        // ---- load A tile (64 x 16), apply the -0.5 centering here ----
        {
            float4 av = *reinterpret_cast<const float4*>(
                &samples[(size_t)(blockB + arow) * F_ + k0 + akg]);
            As[arow][akg + 0] = av.x - 0.5f;
            As[arow][akg + 1] = av.y - 0.5f;
            As[arow][akg + 2] = av.z - 0.5f;
            As[arow][akg + 3] = av.w - 0.5f;
        }
        // ---- load B tile (16 x 256) from bhv[d][k], transpose into Bs[k][d] ----
        #pragma unroll
        for (int q = 0; q < 4; q++) {
            int linear = tid + 256 * q;        // 0..1023
            int didx   = linear >> 2;          // 0..255
            int kg     = (linear & 3) * 4;     // 0,4,8,12
            int d      = blockD + didx;
            float4 bv = make_float4(0.f, 0.f, 0.f, 0.f);
            if (d < D_)
                bv = *reinterpret_cast<const float4*>(&bhv[(size_t)d * F_ + k0 + kg]);
            Bs[kg + 0][didx] = bv.x;
            Bs[kg + 1][didx] = bv.y;
            Bs[kg + 2][didx] = bv.z;
            Bs[kg + 3][didx] = bv.w;
        }
        __syncthreads();

        // ---- FMA core: 64 FFMA per thread per k ----
        #pragma unroll
        for (int k = 0; k < BK; k++) {
            float bbv[4];
            #pragma unroll
            for (int j = 0; j < 4; j++)
                bbv[j] = Bs[k][wd + lane + 32 * j];
            float a[16];
            #pragma unroll
            for (int i = 0; i < 16; i++)
                a[i] = As[wb + i][k];
            #pragma unroll
            for (int i = 0; i < 16; i++)
                #pragma unroll
                for (int j = 0; j < 4; j++)
                    acc[i][j] = fmaf(a[i], bbv[j], acc[i][j]);
        }
        __syncthreads();
    }

    // ---- epilogue: binarize via ballot, XOR-popcount vs packed centroids ----
    int cnt[16];
    #pragma unroll
    for (int i = 0; i < 16; i++) cnt[i] = 0;

    #pragma unroll
    for (int j = 0; j < 4; j++) {
        int dstart = blockD + wd + 32 * j;
        int rem = D_ - dstart;
        unsigned mask = (rem >= 32) ? 0xFFFFFFFFu
                       : (rem <= 0) ? 0u
                       : ((1u << rem) - 1u);
        int dw = dstart >> 5;
        unsigned cw = 0u;
        if (lane < C_ && mask != 0u)
            cw = g_centPacked[lane * NW + dw];
        #pragma unroll
        for (int i = 0; i < 16; i++) {
            unsigned word = __ballot_sync(0xFFFFFFFFu, acc[i][j] > 0.0f);
            if (lane < C_)
                cnt[i] += __popc((word ^ cw) & mask);
        }
    }

    if (lane < C_) {
        #pragma unroll
        for (int i = 0; i < 16; i++) {
            atomicAdd(&out[(size_t)(blockB + wb + i) * C_ + lane], -(float)cnt[i]);
        }
    }
}

// ---------------------------------------------------------------------------
extern "C" void kernel_launch(void* const* d_in, const int* in_sizes, int n_in,
                              void* d_out, int out_size) {
    const float* samples = (const float*)d_in[0];   // [4096, 784]
    const float* bhv     = (const float*)d_in[1];   // [10000, 784]
    const float* cent    = (const float*)d_in[2];   // [10, 10000]
    float* out = (float*)d_out;                     // [4096, 10]

    pack_centroids_kernel<<<(C_ * NW + 255) / 256, 256>>>(cent);
    zero_out_kernel<<<(B_ * C_ + 255) / 256, 256>>>(out);

    dim3 grid((D_ + BN - 1) / BN, B_ / BM);   // (40, 64)
    hdc_fused_kernel<<<grid, 256>>>(samples, bhv, out);
}

// round 3
// speedup vs baseline: 2.1609x; 2.1609x over previous
#include <cuda_runtime.h>
#include <cuda_bf16.h>
#include <cstdint>

// ---------------------------------------------------------------------------
// Problem constants
// ---------------------------------------------------------------------------
#define B_    4096
#define F_    784
#define D_    10000
#define C_    10
#define NW    313            // ceil(D/32) packed centroid words per class

// 3-term bf16 split GEMM: K' = 3*784 = 2352, padded to 74*32 = 2368
#define KP    2368
#define KP2   (KP * 2)       // row bytes in bf16 scratch
#define KSEG  784
#define NPAD  10240          // 40 * 256

// Tiling
#define TM      128
#define TN      256
#define BK      32           // bf16 elems per K-chunk
#define NCHUNK  (KP / BK)    // 74
#define THREADS 512
#define STAGES  3

// Padded smem rows: 32 bf16 (64B) + 16B pad = 80B (conflict-free for ldmatrix)
#define RSB         80
#define A_ROWS      TM
#define BROWS       TN
#define STAGE_BYTES ((A_ROWS + BROWS) * RSB)     // 30720
#define SMEM_BYTES  (STAGES * STAGE_BYTES)       // 92160

// ---------------------------------------------------------------------------
// Device scratch (allocation-free: __device__ globals)
// ---------------------------------------------------------------------------
__device__ unsigned g_centPacked[C_ * NW];
__device__ __align__(16) __nv_bfloat16 g_Asp[(size_t)B_ * KP];     // 19.4 MB
__device__ __align__(16) __nv_bfloat16 g_Bsp[(size_t)NPAD * KP];   // 48.5 MB

// ---------------------------------------------------------------------------
// PTX helpers (sm_100 baseline: cp.async + ldmatrix + mma.sync only)
// ---------------------------------------------------------------------------
__device__ __forceinline__ uint32_t smem_u32(const void* p) {
    uint32_t a;
    asm("{ .reg .u64 t; cvta.to.shared.u64 t, %1; cvt.u32.u64 %0, t; }"
        : "=r"(a) : "l"(p));
    return a;
}

#define CP_ASYNC16(dst, src) \
    asm volatile("cp.async.cg.shared.global [%0], [%1], 16;" \
                 :: "r"(dst), "l"(src) : "memory")
#define CP_COMMIT() asm volatile("cp.async.commit_group;" ::: "memory")
#define CP_WAIT1()  asm volatile("cp.async.wait_group 1;" ::: "memory")
#define CP_WAIT0()  asm volatile("cp.async.wait_group 0;" ::: "memory")

#define LDMATRIX_X4(r0, r1, r2, r3, addr)                                     \
    asm volatile("ldmatrix.sync.aligned.m8n8.x4.shared.b16 {%0,%1,%2,%3}, [%4];" \
                 : "=r"(r0), "=r"(r1), "=r"(r2), "=r"(r3) : "r"(addr))

#define MMA16816(d0, d1, d2, d3, a0, a1, a2, a3, b0, b1)                      \
    asm volatile("mma.sync.aligned.m16n8k16.row.col.f32.bf16.bf16.f32 "       \
                 "{%0,%1,%2,%3}, {%4,%5,%6,%7}, {%8,%9}, {%0,%1,%2,%3};"      \
                 : "+f"(d0), "+f"(d1), "+f"(d2), "+f"(d3)                     \
                 : "r"(a0), "r"(a1), "r"(a2), "r"(a3), "r"(b0), "r"(b1))

// ---------------------------------------------------------------------------
// Prep kernels
// ---------------------------------------------------------------------------
// A' row layout: [0,784)=hi(x-0.5), [784,1568)=lo(x-0.5), [1568,2352)=hi, pad 0
__global__ void prep_A_kernel(const float* __restrict__ samples) {
    size_t idx = (size_t)blockIdx.x * blockDim.x + threadIdx.x;
    if (idx >= (size_t)B_ * KP) return;
    int r = (int)(idx / KP), k = (int)(idx % KP);
    __nv_bfloat16 v = __float2bfloat16(0.0f);
    if (k < 3 * KSEG) {
        int f = k % KSEG, seg = k / KSEG;
        float x = samples[(size_t)r * F_ + f] - 0.5f;
        __nv_bfloat16 hi = __float2bfloat16(x);
        v = (seg == 1) ? __float2bfloat16(x - __bfloat162float(hi)) : hi;
    }
    g_Asp[idx] = v;
}

// B' row layout: [0,784)=hi(w), [784,1568)=hi(w), [1568,2352)=lo(w), pad 0
// => A'.B' = Ahi.Bhi + Alo.Bhi + Ahi.Blo  (3-term fp32-split product)
__global__ void prep_B_kernel(const float* __restrict__ bhv) {
    size_t idx = (size_t)blockIdx.x * blockDim.x + threadIdx.x;
    if (idx >= (size_t)NPAD * KP) return;
    int r = (int)(idx / KP), k = (int)(idx % KP);
    __nv_bfloat16 v = __float2bfloat16(0.0f);
    if (r < D_ && k < 3 * KSEG) {
        int f = k % KSEG, seg = k / KSEG;
        float w = bhv[(size_t)r * F_ + f];
        __nv_bfloat16 hi = __float2bfloat16(w);
        v = (seg == 2) ? __float2bfloat16(w - __bfloat162float(hi)) : hi;
    }
    g_Bsp[idx] = v;
}

__global__ void pack_centroids_kernel(const float* __restrict__ cent) {
    int idx = blockIdx.x * blockDim.x + threadIdx.x;
    if (idx >= C_ * NW) return;
    int c = idx / NW, w = idx % NW, d0 = w * 32;
    unsigned word = 0u;
    #pragma unroll
    for (int b = 0; b < 32; b++) {
        int d = d0 + b;
        if (d < D_ && cent[(size_t)c * D_ + d] > 0.5f) word |= (1u << b);
    }
    g_centPacked[idx] = word;
}

__global__ void zero_out_kernel(float* __restrict__ out) {
    int i = blockIdx.x * blockDim.x + threadIdx.x;
    if (i < B_ * C_) out[i] = 0.0f;
}

// ---------------------------------------------------------------------------
// Main kernel: bf16 mma.sync GEMM (M=128, N=256 per CTA, K=2368) with fused
// sign-binarize / XOR-popcount / per-class Hamming epilogue.
// 16 warps: warpM = wid/4 (4 x 32 rows), warpN = wid%4 (4 x 64 cols).
// ---------------------------------------------------------------------------
__global__ void __launch_bounds__(THREADS, 1)
hdc_mma_kernel(float* __restrict__ out) {
    extern __shared__ char smem[];
    const uint32_t sbase = smem_u32(smem);
    const int tid   = threadIdx.x;
    const int wid   = tid >> 5;
    const int lane  = tid & 31;
    const int warpM = wid >> 2;
    const int warpN = wid & 3;
    const int bm = blockIdx.y * TM;
    const int bn = blockIdx.x * TN;

    const char* Abase = (const char*)(g_Asp + (size_t)bm * KP);
    const char* Bbase = (const char*)(g_Bsp + (size_t)bn * KP);

    float acc[2][8][4];
    #pragma unroll
    for (int i = 0; i < 2; i++)
        #pragma unroll
        for (int j = 0; j < 8; j++)
            #pragma unroll
            for (int e = 0; e < 4; e++)
                acc[i][j][e] = 0.0f;

    // ---- cp.async chunk loader: 1536 x 16B granules, 3 per thread ----
    auto load_chunk = [&](int c, int s) {
        uint32_t stage = sbase + s * STAGE_BYTES;
        #pragma unroll
        for (int i = 0; i < 3; i++) {
            int g   = tid + THREADS * i;       // 0..1535
            int row = g >> 2;
            int seg = g & 3;
            if (row < A_ROWS) {
                CP_ASYNC16(stage + row * RSB + seg * 16,
                           Abase + (size_t)row * KP2 + c * (BK * 2) + seg * 16);
            } else {
                int r2 = row - A_ROWS;
                CP_ASYNC16(stage + A_ROWS * RSB + r2 * RSB + seg * 16,
                           Bbase + (size_t)r2 * KP2 + c * (BK * 2) + seg * 16);
            }
        }
    };

    // ---- prologue: fill STAGES-1 stages ----
    #pragma unroll
    for (int p = 0; p < STAGES - 1; p++) {
        load_chunk(p, p);
        CP_COMMIT();
    }

    // ldmatrix base addresses (per warp)
    const uint32_t aRowSel = (lane & 15);
    const uint32_t aKByte  = (lane >> 4) * 16;
    const uint32_t bRowSel = ((lane >> 4) << 3) + (lane & 7);
    const uint32_t bKByte  = ((lane >> 3) & 1) * 16;

    for (int c = 0; c < NCHUNK; c++) {
        int s = c % STAGES;
        if (c + 1 < NCHUNK) CP_WAIT1(); else CP_WAIT0();
        __syncthreads();   // stage s data visible; stage (c-1)%S compute done CTA-wide

        int cn = c + STAGES - 1;
        if (cn < NCHUNK) {
            load_chunk(cn, cn % STAGES);
            CP_COMMIT();
        }

        uint32_t sA = sbase + s * STAGE_BYTES + (warpM * 32) * RSB;
        uint32_t sB = sbase + s * STAGE_BYTES + A_ROWS * RSB + (warpN * 64) * RSB;

        #pragma unroll
        for (int ks = 0; ks < 2; ks++) {
            uint32_t a[2][4];
            #pragma unroll
            for (int i = 0; i < 2; i++) {
                uint32_t addr = sA + (i * 16 + aRowSel) * RSB + ks * 32 + aKByte;
                LDMATRIX_X4(a[i][0], a[i][1], a[i][2], a[i][3], addr);
            }
            uint32_t b[4][4];
            #pragma unroll
            for (int jj = 0; jj < 4; jj++) {
                uint32_t addr = sB + (jj * 16 + bRowSel) * RSB + ks * 32 + bKByte;
                LDMATRIX_X4(b[jj][0], b[jj][1], b[jj][2], b[jj][3], addr);
            }
            #pragma unroll
            for (int i = 0; i < 2; i++)
                #pragma unroll
                for (int jj = 0; jj < 4; jj++) {
                    MMA16816(acc[i][2*jj][0], acc[i][2*jj][1], acc[i][2*jj][2], acc[i][2*jj][3],
                             a[i][0], a[i][1], a[i][2], a[i][3], b[jj][0], b[jj][1]);
                    MMA16816(acc[i][2*jj+1][0], acc[i][2*jj+1][1], acc[i][2*jj+1][2], acc[i][2*jj+1][3],
                             a[i][0], a[i][1], a[i][2], a[i][3], b[jj][2], b[jj][3]);
                }
        }
    }

    // =======================================================================
    // Epilogue
    // =======================================================================
    __syncthreads();   // stage buffers free -> reuse as sign board (128x256 bytes)

    // Phase 1: dump sign bytes. signs[row][col] at smem offset row*256+col.
    {
        int rbase = warpM * 32 + (lane >> 2);
        int cbase = warpN * 64 + ((lane & 3) << 1);
        #pragma unroll
        for (int i = 0; i < 2; i++)
            #pragma unroll
            for (int j = 0; j < 8; j++)
                #pragma unroll
                for (int e = 0; e < 4; e++) {
                    int row = rbase + i * 16 + ((e >> 1) << 3);
                    int col = cbase + j * 8 + (e & 1);
                    smem[row * 256 + col] = (acc[i][j][e] > 0.0f) ? 1 : 0;
                }
    }
    __syncthreads();

    // Phase 2: pack 32 sign bytes -> word, XOR-popcount vs packed centroids.
    // Thread t handles row = t/4, two 32-col words w = (t%4)*2 + {0,1}.
    {
        int row = tid >> 2;
        int cnt[C_];
        #pragma unroll
        for (int c = 0; c < C_; c++) cnt[c] = 0;

        #pragma unroll
        for (int q = 0; q < 2; q++) {
            int w = ((tid & 3) << 1) + q;
            const uint32_t* p = (const uint32_t*)(smem + row * 256 + w * 32);
            unsigned word = 0u;
            #pragma unroll
            for (int x = 0; x < 8; x++) {
                unsigned nib = ((p[x] & 0x01010101u) * 0x01020408u) >> 24;  // bit i = byte i
                word |= (nib & 0xFu) << (4 * x);
            }
            int dw = (bn >> 5) + w;
            if (dw < NW) {
                #pragma unroll
                for (int c = 0; c < C_; c++)
                    cnt[c] += __popc(word ^ g_centPacked[c * NW + dw]);
            }
        }
        // reduce over the 4 threads of the quad (same row, 8 words total)
        #pragma unroll
        for (int c = 0; c < C_; c++) {
            cnt[c] += __shfl_xor_sync(0xFFFFFFFFu, cnt[c], 1);
            cnt[c] += __shfl_xor_sync(0xFFFFFFFFu, cnt[c], 2);
        }
        if ((lane & 3) == 0) {
            #pragma unroll
            for (int c = 0; c < C_; c++)
                atomicAdd(&out[(size_t)(bm + row) * C_ + c], -(float)cnt[c]);
        }
    }
}

// ---------------------------------------------------------------------------
extern "C" void kernel_launch(void* const* d_in, const int* in_sizes, int n_in,
                              void* d_out, int out_size) {
    const float* samples = (const float*)d_in[0];   // [4096, 784]
    const float* bhv     = (const float*)d_in[1];   // [10000, 784]
    const float* cent    = (const float*)d_in[2];   // [10, 10000]
    float* out = (float*)d_out;                     // [4096, 10]

    cudaFuncSetAttribute(hdc_mma_kernel,
                         cudaFuncAttributeMaxDynamicSharedMemorySize, SMEM_BYTES);

    {
        size_t n = (size_t)B_ * KP;
        prep_A_kernel<<<(unsigned)((n + 255) / 256), 256>>>(samples);
    }
    {
        size_t n = (size_t)NPAD * KP;
        prep_B_kernel<<<(unsigned)((n + 255) / 256), 256>>>(bhv);
    }
    pack_centroids_kernel<<<(C_ * NW + 255) / 256, 256>>>(cent);
    zero_out_kernel<<<(B_ * C_ + 255) / 256, 256>>>(out);

    dim3 grid(NPAD / TN, B_ / TM);   // (40, 32)
    hdc_mma_kernel<<<grid, THREADS, SMEM_BYTES>>>(out);
}

// round 4
// speedup vs baseline: 3.1179x; 1.4428x over previous
#include <cuda_runtime.h>
#include <cuda_fp16.h>
#include <cstdint>

// ---------------------------------------------------------------------------
// Problem constants
// ---------------------------------------------------------------------------
#define B_    4096
#define F_    784
#define D_    10000
#define C_    10
#define NW    313            // ceil(D/32) packed centroid words per class

// 2-term fp16 split GEMM:
//   A' rows: [0,800)=hi(x-0.5) (f<784, else 0), [800,1600)=lo(x-0.5)
//   B  rows: [0,800)=fp16(w)   (f<784, else 0)      -- used by BOTH A segments
// A'.B(k%800) = Ahi.Bhi + Alo.Bhi ; dropped residual x.(w-fp16(w)) ~ 1e-3 rms
#define KPA   1600
#define KPB   800
#define SEGC  25             // chunks per 800-elem segment (BK=32)
#define KSEG  784
#define NPAD  10240          // 40 * 256

// Tiling
#define TM      128
#define TN      256
#define BK      32           // fp16 elems per K-chunk
#define NCHUNK  (KPA / BK)   // 50
#define THREADS 512
#define STAGES  3

// Padded smem rows: 32 fp16 (64B) + 16B pad = 80B (conflict-free for ldmatrix)
#define RSB         80
#define A_ROWS      TM
#define BROWS       TN
#define STAGE_BYTES ((A_ROWS + BROWS) * RSB)     // 30720
#define SMEM_BYTES  (STAGES * STAGE_BYTES)       // 92160

// ---------------------------------------------------------------------------
// Device scratch (allocation-free: __device__ globals)
// ---------------------------------------------------------------------------
__device__ unsigned g_centPacked[C_ * NW];
__device__ __align__(16) __half g_Asp[(size_t)B_ * KPA];     // 13.1 MB
__device__ __align__(16) __half g_Bsp[(size_t)NPAD * KPB];   // 16.4 MB

// ---------------------------------------------------------------------------
// PTX helpers (sm_100 baseline: cp.async + ldmatrix + mma.sync only)
// ---------------------------------------------------------------------------
__device__ __forceinline__ uint32_t smem_u32(const void* p) {
    uint32_t a;
    asm("{ .reg .u64 t; cvta.to.shared.u64 t, %1; cvt.u32.u64 %0, t; }"
        : "=r"(a) : "l"(p));
    return a;
}

#define CP_ASYNC16(dst, src) \
    asm volatile("cp.async.cg.shared.global [%0], [%1], 16;" \
                 :: "r"(dst), "l"(src) : "memory")
#define CP_COMMIT() asm volatile("cp.async.commit_group;" ::: "memory")
#define CP_WAIT1()  asm volatile("cp.async.wait_group 1;" ::: "memory")
#define CP_WAIT0()  asm volatile("cp.async.wait_group 0;" ::: "memory")

#define LDMATRIX_X4(r0, r1, r2, r3, addr)                                     \
    asm volatile("ldmatrix.sync.aligned.m8n8.x4.shared.b16 {%0,%1,%2,%3}, [%4];" \
                 : "=r"(r0), "=r"(r1), "=r"(r2), "=r"(r3) : "r"(addr))

#define MMA16816(d0, d1, d2, d3, a0, a1, a2, a3, b0, b1)                      \
    asm volatile("mma.sync.aligned.m16n8k16.row.col.f32.f16.f16.f32 "         \
                 "{%0,%1,%2,%3}, {%4,%5,%6,%7}, {%8,%9}, {%0,%1,%2,%3};"      \
                 : "+f"(d0), "+f"(d1), "+f"(d2), "+f"(d3)                     \
                 : "r"(a0), "r"(a1), "r"(a2), "r"(a3), "r"(b0), "r"(b1))

// ---------------------------------------------------------------------------
// Prep kernels
// ---------------------------------------------------------------------------
__global__ void prep_A_kernel(const float* __restrict__ samples) {
    size_t idx = (size_t)blockIdx.x * blockDim.x + threadIdx.x;
    if (idx >= (size_t)B_ * KPA) return;
    int r = (int)(idx / KPA), k = (int)(idx % KPA);
    int seg = k / KPB, f = k % KPB;
    __half v = __float2half_rn(0.0f);
    if (f < KSEG) {
        float x = samples[(size_t)r * F_ + f] - 0.5f;
        __half hi = __float2half_rn(x);
        v = (seg == 1) ? __float2half_rn(x - __half2float(hi)) : hi;
    }
    g_Asp[idx] = v;
}

__global__ void prep_B_kernel(const float* __restrict__ bhv) {
    size_t idx = (size_t)blockIdx.x * blockDim.x + threadIdx.x;
    if (idx >= (size_t)NPAD * KPB) return;
    int r = (int)(idx / KPB), f = (int)(idx % KPB);
    __half v = __float2half_rn(0.0f);
    if (r < D_ && f < KSEG)
        v = __float2half_rn(bhv[(size_t)r * F_ + f]);
    g_Bsp[idx] = v;
}

__global__ void pack_centroids_kernel(const float* __restrict__ cent) {
    int idx = blockIdx.x * blockDim.x + threadIdx.x;
    if (idx >= C_ * NW) return;
    int c = idx / NW, w = idx % NW, d0 = w * 32;
    unsigned word = 0u;
    #pragma unroll
    for (int b = 0; b < 32; b++) {
        int d = d0 + b;
        if (d < D_ && cent[(size_t)c * D_ + d] > 0.5f) word |= (1u << b);
    }
    g_centPacked[idx] = word;
}

__global__ void zero_out_kernel(float* __restrict__ out) {
    int i = blockIdx.x * blockDim.x + threadIdx.x;
    if (i < B_ * C_) out[i] = 0.0f;
}

// ---------------------------------------------------------------------------
// Main kernel: fp16 mma.sync GEMM (M=128, N=256 per CTA, K=1600 over A,
// B reindexed k%800) with fused sign / XOR-popcount / Hamming epilogue.
// 16 warps: warpM = wid/4 (4 x 32 rows), warpN = wid%4 (4 x 64 cols).
// ---------------------------------------------------------------------------
__global__ void __launch_bounds__(THREADS, 1)
hdc_mma_kernel(float* __restrict__ out) {
    extern __shared__ char smem[];
    const uint32_t sbase = smem_u32(smem);
    const int tid   = threadIdx.x;
    const int wid   = tid >> 5;
    const int lane  = tid & 31;
    const int warpM = wid >> 2;
    const int warpN = wid & 3;
    const int bm = blockIdx.y * TM;
    const int bn = blockIdx.x * TN;

    const char* Abase = (const char*)(g_Asp + (size_t)bm * KPA);
    const char* Bbase = (const char*)(g_Bsp + (size_t)bn * KPB);

    float acc[2][8][4];
    #pragma unroll
    for (int i = 0; i < 2; i++)
        #pragma unroll
        for (int j = 0; j < 8; j++)
            #pragma unroll
            for (int e = 0; e < 4; e++)
                acc[i][j][e] = 0.0f;

    // ---- cp.async chunk loader: 1536 x 16B granules, 3 per thread ----
    // A chunk index = c (K=1600); B chunk index = c % SEGC (K=800, reused).
    auto load_chunk = [&](int c, int s) {
        uint32_t stage = sbase + s * STAGE_BYTES;
        int cb = (c < SEGC) ? c : c - SEGC;
        #pragma unroll
        for (int i = 0; i < 3; i++) {
            int g   = tid + THREADS * i;       // 0..1535
            int row = g >> 2;
            int seg = g & 3;
            if (row < A_ROWS) {
                CP_ASYNC16(stage + row * RSB + seg * 16,
                           Abase + (size_t)row * (KPA * 2) + c * (BK * 2) + seg * 16);
            } else {
                int r2 = row - A_ROWS;
                CP_ASYNC16(stage + A_ROWS * RSB + r2 * RSB + seg * 16,
                           Bbase + (size_t)r2 * (KPB * 2) + cb * (BK * 2) + seg * 16);
            }
        }
    };

    // ---- prologue: fill STAGES-1 stages ----
    #pragma unroll
    for (int p = 0; p < STAGES - 1; p++) {
        load_chunk(p, p);
        CP_COMMIT();
    }

    // ldmatrix base addresses (per warp)
    const uint32_t aRowSel = (lane & 15);
    const uint32_t aKByte  = (lane >> 4) * 16;
    const uint32_t bRowSel = ((lane >> 4) << 3) + (lane & 7);
    const uint32_t bKByte  = ((lane >> 3) & 1) * 16;

    for (int c = 0; c < NCHUNK; c++) {
        int s = c % STAGES;
        if (c + 1 < NCHUNK) CP_WAIT1(); else CP_WAIT0();
        __syncthreads();

        int cn = c + STAGES - 1;
        if (cn < NCHUNK) {
            load_chunk(cn, cn % STAGES);
            CP_COMMIT();
        }

        uint32_t sA = sbase + s * STAGE_BYTES + (warpM * 32) * RSB;
        uint32_t sB = sbase + s * STAGE_BYTES + A_ROWS * RSB + (warpN * 64) * RSB;

        #pragma unroll
        for (int ks = 0; ks < 2; ks++) {
            uint32_t a[2][4];
            #pragma unroll
            for (int i = 0; i < 2; i++) {
                uint32_t addr = sA + (i * 16 + aRowSel) * RSB + ks * 32 + aKByte;
                LDMATRIX_X4(a[i][0], a[i][1], a[i][2], a[i][3], addr);
            }
            uint32_t b[4][4];
            #pragma unroll
            for (int jj = 0; jj < 4; jj++) {
                uint32_t addr = sB + (jj * 16 + bRowSel) * RSB + ks * 32 + bKByte;
                LDMATRIX_X4(b[jj][0], b[jj][1], b[jj][2], b[jj][3], addr);
            }
            #pragma unroll
            for (int i = 0; i < 2; i++)
                #pragma unroll
                for (int jj = 0; jj < 4; jj++) {
                    MMA16816(acc[i][2*jj][0], acc[i][2*jj][1], acc[i][2*jj][2], acc[i][2*jj][3],
                             a[i][0], a[i][1], a[i][2], a[i][3], b[jj][0], b[jj][1]);
                    MMA16816(acc[i][2*jj+1][0], acc[i][2*jj+1][1], acc[i][2*jj+1][2], acc[i][2*jj+1][3],
                             a[i][0], a[i][1], a[i][2], a[i][3], b[jj][2], b[jj][3]);
                }
        }
    }

    // =======================================================================
    // Epilogue
    // =======================================================================
    __syncthreads();   // stage buffers free -> reuse as sign board (128x256 bytes)

    // Phase 1: dump sign bytes. signs[row][col] at smem offset row*256+col.
    {
        int rbase = warpM * 32 + (lane >> 2);
        int cbase = warpN * 64 + ((lane & 3) << 1);
        #pragma unroll
        for (int i = 0; i < 2; i++)
            #pragma unroll
            for (int j = 0; j < 8; j++)
                #pragma unroll
                for (int e = 0; e < 4; e++) {
                    int row = rbase + i * 16 + ((e >> 1) << 3);
                    int col = cbase + j * 8 + (e & 1);
                    smem[row * 256 + col] = (acc[i][j][e] > 0.0f) ? 1 : 0;
                }
    }
    __syncthreads();

    // Phase 2: pack 32 sign bytes -> word, XOR-popcount vs packed centroids.
    {
        int row = tid >> 2;
        int cnt[C_];
        #pragma unroll
        for (int c = 0; c < C_; c++) cnt[c] = 0;

        #pragma unroll
        for (int q = 0; q < 2; q++) {
            int w = ((tid & 3) << 1) + q;
            const uint32_t* p = (const uint32_t*)(smem + row * 256 + w * 32);
            unsigned word = 0u;
            #pragma unroll
            for (int x = 0; x < 8; x++) {
                unsigned nib = ((p[x] & 0x01010101u) * 0x01020408u) >> 24;
                word |= (nib & 0xFu) << (4 * x);
            }
            int dw = (bn >> 5) + w;
            if (dw < NW) {
                #pragma unroll
                for (int c = 0; c < C_; c++)
                    cnt[c] += __popc(word ^ g_centPacked[c * NW + dw]);
            }
        }
        #pragma unroll
        for (int c = 0; c < C_; c++) {
            cnt[c] += __shfl_xor_sync(0xFFFFFFFFu, cnt[c], 1);
            cnt[c] += __shfl_xor_sync(0xFFFFFFFFu, cnt[c], 2);
        }
        if ((lane & 3) == 0) {
            #pragma unroll
            for (int c = 0; c < C_; c++)
                atomicAdd(&out[(size_t)(bm + row) * C_ + c], -(float)cnt[c]);
        }
    }
}

// ---------------------------------------------------------------------------
extern "C" void kernel_launch(void* const* d_in, const int* in_sizes, int n_in,
                              void* d_out, int out_size) {
    const float* samples = (const float*)d_in[0];   // [4096, 784]
    const float* bhv     = (const float*)d_in[1];   // [10000, 784]
    const float* cent    = (const float*)d_in[2];   // [10, 10000]
    float* out = (float*)d_out;                     // [4096, 10]

    cudaFuncSetAttribute(hdc_mma_kernel,
                         cudaFuncAttributeMaxDynamicSharedMemorySize, SMEM_BYTES);

    {
        size_t n = (size_t)B_ * KPA;
        prep_A_kernel<<<(unsigned)((n + 255) / 256), 256>>>(samples);
    }
    {
        size_t n = (size_t)NPAD * KPB;
        prep_B_kernel<<<(unsigned)((n + 255) / 256), 256>>>(bhv);
    }
    pack_centroids_kernel<<<(C_ * NW + 255) / 256, 256>>>(cent);
    zero_out_kernel<<<(B_ * C_ + 255) / 256, 256>>>(out);

    dim3 grid(NPAD / TN, B_ / TM);   // (40, 32)
    hdc_mma_kernel<<<grid, THREADS, SMEM_BYTES>>>(out);
}

// round 5
// speedup vs baseline: 5.6280x; 1.8051x over previous
#include <cuda_runtime.h>
#include <cuda_fp16.h>
#include <cstdint>

// ---------------------------------------------------------------------------
// Problem constants
// ---------------------------------------------------------------------------
#define B_    4096
#define F_    784
#define D_    10000
#define C_    10
#define NW    313            // ceil(D/32) packed centroid words per class

// Single fp16 GEMM: A = fp16(x-0.5) [B_, 800], B = fp16(w) [NPAD, 800].
// Residual (quantization of both sides) has dot-rms ~9e-4 -> sign-flip rate
// ~1.6e-4/elem -> rel_err ~2-3e-4 (calibrated against round-4 measurement).
#define KPK   800
#define KSEG  784
#define NPAD  10240          // 40 * 256

// Tiling
#define TM      128
#define TN      256
#define BK      32           // fp16 elems per K-chunk
#define NCHUNK  (KPK / BK)   // 25
#define THREADS 512
#define STAGES  3

// Padded smem rows: 32 fp16 (64B) + 16B pad = 80B (conflict-free for ldmatrix)
#define RSB         80
#define A_ROWS      TM
#define BROWS       TN
#define STAGE_BYTES ((A_ROWS + BROWS) * RSB)     // 30720
#define SMEM_BYTES  (STAGES * STAGE_BYTES)       // 92160

// ---------------------------------------------------------------------------
// Device scratch (allocation-free: __device__ globals)
// ---------------------------------------------------------------------------
__device__ unsigned g_centPacked[C_ * NW];
__device__ __align__(16) __half g_Asp[(size_t)B_ * KPK];     // 6.6 MB
__device__ __align__(16) __half g_Bsp[(size_t)NPAD * KPK];   // 16.4 MB

// ---------------------------------------------------------------------------
// PTX helpers (sm_100 baseline: cp.async + ldmatrix + mma.sync only)
// ---------------------------------------------------------------------------
__device__ __forceinline__ uint32_t smem_u32(const void* p) {
    uint32_t a;
    asm("{ .reg .u64 t; cvta.to.shared.u64 t, %1; cvt.u32.u64 %0, t; }"
        : "=r"(a) : "l"(p));
    return a;
}

#define CP_ASYNC16(dst, src) \
    asm volatile("cp.async.cg.shared.global [%0], [%1], 16;" \
                 :: "r"(dst), "l"(src) : "memory")
#define CP_COMMIT() asm volatile("cp.async.commit_group;" ::: "memory")
#define CP_WAIT1()  asm volatile("cp.async.wait_group 1;" ::: "memory")
#define CP_WAIT0()  asm volatile("cp.async.wait_group 0;" ::: "memory")

#define LDMATRIX_X4(r0, r1, r2, r3, addr)                                     \
    asm volatile("ldmatrix.sync.aligned.m8n8.x4.shared.b16 {%0,%1,%2,%3}, [%4];" \
                 : "=r"(r0), "=r"(r1), "=r"(r2), "=r"(r3) : "r"(addr))

#define MMA16816(d0, d1, d2, d3, a0, a1, a2, a3, b0, b1)                      \
    asm volatile("mma.sync.aligned.m16n8k16.row.col.f32.f16.f16.f32 "         \
                 "{%0,%1,%2,%3}, {%4,%5,%6,%7}, {%8,%9}, {%0,%1,%2,%3};"      \
                 : "+f"(d0), "+f"(d1), "+f"(d2), "+f"(d3)                     \
                 : "r"(a0), "r"(a1), "r"(a2), "r"(a3), "r"(b0), "r"(b1))

// ---------------------------------------------------------------------------
// Prep kernels
// ---------------------------------------------------------------------------
__global__ void prep_A_kernel(const float* __restrict__ samples) {
    size_t idx = (size_t)blockIdx.x * blockDim.x + threadIdx.x;
    if (idx >= (size_t)B_ * KPK) return;
    int r = (int)(idx / KPK), f = (int)(idx % KPK);
    __half v = __float2half_rn(0.0f);
    if (f < KSEG)
        v = __float2half_rn(samples[(size_t)r * F_ + f] - 0.5f);
    g_Asp[idx] = v;
}

__global__ void prep_B_kernel(const float* __restrict__ bhv) {
    size_t idx = (size_t)blockIdx.x * blockDim.x + threadIdx.x;
    if (idx >= (size_t)NPAD * KPK) return;
    int r = (int)(idx / KPK), f = (int)(idx % KPK);
    __half v = __float2half_rn(0.0f);
    if (r < D_ && f < KSEG)
        v = __float2half_rn(bhv[(size_t)r * F_ + f]);
    g_Bsp[idx] = v;
}

__global__ void pack_centroids_kernel(const float* __restrict__ cent) {
    int idx = blockIdx.x * blockDim.x + threadIdx.x;
    if (idx >= C_ * NW) return;
    int c = idx / NW, w = idx % NW, d0 = w * 32;
    unsigned word = 0u;
    #pragma unroll
    for (int b = 0; b < 32; b++) {
        int d = d0 + b;
        if (d < D_ && cent[(size_t)c * D_ + d] > 0.5f) word |= (1u << b);
    }
    g_centPacked[idx] = word;
}

__global__ void zero_out_kernel(float* __restrict__ out) {
    int i = blockIdx.x * blockDim.x + threadIdx.x;
    if (i < B_ * C_) out[i] = 0.0f;
}

// ---------------------------------------------------------------------------
// Main kernel: fp16 mma.sync GEMM (M=128, N=256 per CTA, K=800) with fused
// sign-binarize / XOR-popcount / per-class Hamming epilogue.
// 16 warps: warpM = wid/4 (4 x 32 rows), warpN = wid%4 (4 x 64 cols).
// ---------------------------------------------------------------------------
__global__ void __launch_bounds__(THREADS, 1)
hdc_mma_kernel(float* __restrict__ out) {
    extern __shared__ char smem[];
    const uint32_t sbase = smem_u32(smem);
    const int tid   = threadIdx.x;
    const int wid   = tid >> 5;
    const int lane  = tid & 31;
    const int warpM = wid >> 2;
    const int warpN = wid & 3;
    const int bm = blockIdx.y * TM;
    const int bn = blockIdx.x * TN;

    const char* Abase = (const char*)(g_Asp + (size_t)bm * KPK);
    const char* Bbase = (const char*)(g_Bsp + (size_t)bn * KPK);

    float acc[2][8][4];
    #pragma unroll
    for (int i = 0; i < 2; i++)
        #pragma unroll
        for (int j = 0; j < 8; j++)
            #pragma unroll
            for (int e = 0; e < 4; e++)
                acc[i][j][e] = 0.0f;

    // ---- cp.async chunk loader: 1536 x 16B granules, 3 per thread ----
    auto load_chunk = [&](int c, int s) {
        uint32_t stage = sbase + s * STAGE_BYTES;
        #pragma unroll
        for (int i = 0; i < 3; i++) {
            int g   = tid + THREADS * i;       // 0..1535
            int row = g >> 2;
            int seg = g & 3;
            if (row < A_ROWS) {
                CP_ASYNC16(stage + row * RSB + seg * 16,
                           Abase + (size_t)row * (KPK * 2) + c * (BK * 2) + seg * 16);
            } else {
                int r2 = row - A_ROWS;
                CP_ASYNC16(stage + A_ROWS * RSB + r2 * RSB + seg * 16,
                           Bbase + (size_t)r2 * (KPK * 2) + c * (BK * 2) + seg * 16);
            }
        }
    };

    // ---- prologue: fill STAGES-1 stages ----
    #pragma unroll
    for (int p = 0; p < STAGES - 1; p++) {
        load_chunk(p, p);
        CP_COMMIT();
    }

    // ldmatrix base addresses (per warp)
    const uint32_t aRowSel = (lane & 15);
    const uint32_t aKByte  = (lane >> 4) * 16;
    const uint32_t bRowSel = ((lane >> 4) << 3) + (lane & 7);
    const uint32_t bKByte  = ((lane >> 3) & 1) * 16;

    for (int c = 0; c < NCHUNK; c++) {
        int s = c % STAGES;
        if (c + 1 < NCHUNK) CP_WAIT1(); else CP_WAIT0();
        __syncthreads();

        int cn = c + STAGES - 1;
        if (cn < NCHUNK) {
            load_chunk(cn, cn % STAGES);
            CP_COMMIT();
        }

        uint32_t sA = sbase + s * STAGE_BYTES + (warpM * 32) * RSB;
        uint32_t sB = sbase + s * STAGE_BYTES + A_ROWS * RSB + (warpN * 64) * RSB;

        #pragma unroll
        for (int ks = 0; ks < 2; ks++) {
            uint32_t a[2][4];
            #pragma unroll
            for (int i = 0; i < 2; i++) {
                uint32_t addr = sA + (i * 16 + aRowSel) * RSB + ks * 32 + aKByte;
                LDMATRIX_X4(a[i][0], a[i][1], a[i][2], a[i][3], addr);
            }
            uint32_t b[4][4];
            #pragma unroll
            for (int jj = 0; jj < 4; jj++) {
                uint32_t addr = sB + (jj * 16 + bRowSel) * RSB + ks * 32 + bKByte;
                LDMATRIX_X4(b[jj][0], b[jj][1], b[jj][2], b[jj][3], addr);
            }
            #pragma unroll
            for (int i = 0; i < 2; i++)
                #pragma unroll
                for (int jj = 0; jj < 4; jj++) {
                    MMA16816(acc[i][2*jj][0], acc[i][2*jj][1], acc[i][2*jj][2], acc[i][2*jj][3],
                             a[i][0], a[i][1], a[i][2], a[i][3], b[jj][0], b[jj][1]);
                    MMA16816(acc[i][2*jj+1][0], acc[i][2*jj+1][1], acc[i][2*jj+1][2], acc[i][2*jj+1][3],
                             a[i][0], a[i][1], a[i][2], a[i][3], b[jj][2], b[jj][3]);
                }
        }
    }

    // =======================================================================
    // Epilogue
    // =======================================================================
    __syncthreads();   // stage buffers free -> reuse as sign board (128x256 bytes)

    // Phase 1: dump sign bytes. signs[row][col] at smem offset row*256+col.
    {
        int rbase = warpM * 32 + (lane >> 2);
        int cbase = warpN * 64 + ((lane & 3) << 1);
        #pragma unroll
        for (int i = 0; i < 2; i++)
            #pragma unroll
            for (int j = 0; j < 8; j++)
                #pragma unroll
                for (int e = 0; e < 4; e++) {
                    int row = rbase + i * 16 + ((e >> 1) << 3);
                    int col = cbase + j * 8 + (e & 1);
                    smem[row * 256 + col] = (acc[i][j][e] > 0.0f) ? 1 : 0;
                }
    }
    __syncthreads();

    // Phase 2: pack 32 sign bytes -> word, XOR-popcount vs packed centroids.
    {
        int row = tid >> 2;
        int cnt[C_];
        #pragma unroll
        for (int c = 0; c < C_; c++) cnt[c] = 0;

        #pragma unroll
        for (int q = 0; q < 2; q++) {
            int w = ((tid & 3) << 1) + q;
            const uint32_t* p = (const uint32_t*)(smem + row * 256 + w * 32);
            unsigned word = 0u;
            #pragma unroll
            for (int x = 0; x < 8; x++) {
                unsigned nib = ((p[x] & 0x01010101u) * 0x01020408u) >> 24;
                word |= (nib & 0xFu) << (4 * x);
            }
            int dw = (bn >> 5) + w;
            if (dw < NW) {
                #pragma unroll
                for (int c = 0; c < C_; c++)
                    cnt[c] += __popc(word ^ g_centPacked[c * NW + dw]);
            }
        }
        #pragma unroll
        for (int c = 0; c < C_; c++) {
            cnt[c] += __shfl_xor_sync(0xFFFFFFFFu, cnt[c], 1);
            cnt[c] += __shfl_xor_sync(0xFFFFFFFFu, cnt[c], 2);
        }
        if ((lane & 3) == 0) {
            #pragma unroll
            for (int c = 0; c < C_; c++)
                atomicAdd(&out[(size_t)(bm + row) * C_ + c], -(float)cnt[c]);
        }
    }
}

// ---------------------------------------------------------------------------
extern "C" void kernel_launch(void* const* d_in, const int* in_sizes, int n_in,
                              void* d_out, int out_size) {
    const float* samples = (const float*)d_in[0];   // [4096, 784]
    const float* bhv     = (const float*)d_in[1];   // [10000, 784]
    const float* cent    = (const float*)d_in[2];   // [10, 10000]
    float* out = (float*)d_out;                     // [4096, 10]

    cudaFuncSetAttribute(hdc_mma_kernel,
                         cudaFuncAttributeMaxDynamicSharedMemorySize, SMEM_BYTES);

    {
        size_t n = (size_t)B_ * KPK;
        prep_A_kernel<<<(unsigned)((n + 255) / 256), 256>>>(samples);
    }
    {
        size_t n = (size_t)NPAD * KPK;
        prep_B_kernel<<<(unsigned)((n + 255) / 256), 256>>>(bhv);
    }
    pack_centroids_kernel<<<(C_ * NW + 255) / 256, 256>>>(cent);
    zero_out_kernel<<<(B_ * C_ + 255) / 256, 256>>>(out);

    dim3 grid(NPAD / TN, B_ / TM);   // (40, 32)
    hdc_mma_kernel<<<grid, THREADS, SMEM_BYTES>>>(out);
}